// round 13
// baseline (speedup 1.0000x reference)
#include <cuda_runtime.h>
#include <cuda_fp16.h>
#include <cstdint>
#include <math.h>

#define BS 512
#define NN 128
#define HEADS 8
#define DIN 64
#define DOUT 64

// ---- dynamic smem word layout ----
// Phase A staging (dead after GEMM1):
//   A_F  [128 rows][36 words] fp16 h              [0, 4608)
//   B_HI [64 n][36 words] fp16 hi(w)              [4608, 6912)
//   B_LO [64 n][36 words] fp16 lo(w)              [6912, 9216)
// Phase B (overlays staging):
//   P    [128 i][36 words] fp16 exp, one 64-j half at a time   [0, 4608)
//   HT   [64 o][68 words] fp16 h_prime^T (full K=128)          [4608, 8960)
//   RED  ps[256] pd[256] temps; DEN[128] reuse                 [8960, 9472)
// persistent:
#define PLANE_STRIDE 36
#define A_F_W  0
#define B_HI_W 4608
#define B_LO_W 6912
#define P_W    0
#define HT_W   4608
#define RED_W  8960
#define DEN_W  8960
#define SRC_W  9472
#define DST_W  9600
#define BIAS_W 9728
#define TOTAL_W 9792
#define DSMEM_BYTES (TOTAL_W * 4)

__device__ __forceinline__ float tanh_fast(float x) {
    float y;
    asm("tanh.approx.f32 %0, %1;" : "=f"(y) : "f"(x));
    return y;
}
__device__ __forceinline__ uint32_t smem_u32(const void* p) {
    return (uint32_t)__cvta_generic_to_shared(p);
}
__device__ __forceinline__ void mma_fp16(float c[4], const uint32_t a[4], const uint32_t b[2]) {
    asm volatile(
        "mma.sync.aligned.m16n8k16.row.col.f32.f16.f16.f32 "
        "{%0,%1,%2,%3}, {%4,%5,%6,%7}, {%8,%9}, {%0,%1,%2,%3};"
        : "+f"(c[0]), "+f"(c[1]), "+f"(c[2]), "+f"(c[3])
        : "r"(a[0]), "r"(a[1]), "r"(a[2]), "r"(a[3]), "r"(b[0]), "r"(b[1]));
}
__device__ __forceinline__ void ldsm4(uint32_t* r, uint32_t a) {
    asm volatile("ldmatrix.sync.aligned.m8n8.x4.shared.b16 {%0,%1,%2,%3}, [%4];"
                 : "=r"(r[0]), "=r"(r[1]), "=r"(r[2]), "=r"(r[3]) : "r"(a));
}

__global__ __launch_bounds__(256, 5)
void gat_tc6(const float* __restrict__ h,
             const int* __restrict__ adj,
             const float* __restrict__ w,
             const float* __restrict__ a_src,
             const float* __restrict__ a_dst,
             const float* __restrict__ bias,
             float* __restrict__ out)
{
    extern __shared__ uint32_t dsw[];
    float* dsf = (float*)dsw;

    const int bh   = blockIdx.x;
    const int b    = bh >> 3;
    const int head = bh & 7;
    const int tid  = threadIdx.x;
    const int lane = tid & 31;
    const int wid  = tid >> 5;

    if (tid < DOUT) dsf[BIAS_W + tid] = bias[tid];

    // ---- stage A = h[b] (128x64) -> single fp16 plane ----
    {
        const float4* hg4 = (const float4*)(h + (size_t)b * NN * DIN);
        #pragma unroll
        for (int m = 0; m < 8; m++) {
            int i4  = tid + 256 * m;
            int row = i4 >> 4;
            int c4  = i4 & 15;
            float4 v = hg4[i4];
            __half2 h01 = __floats2half2_rn(v.x, v.y);
            __half2 h23 = __floats2half2_rn(v.z, v.w);
            *(uint2*)(dsw + A_F_W + row * PLANE_STRIDE + c4 * 2) =
                make_uint2(*(uint32_t*)&h01, *(uint32_t*)&h23);
        }
    }
    // ---- stage B = w[head] ([k][n]) -> transposed fp16 hi/lo planes [n][k] ----
    {
        const float4* wg4 = (const float4*)(w + (size_t)head * DIN * DOUT);
        __half* bh16 = (__half*)(dsw + B_HI_W);
        __half* bl16 = (__half*)(dsw + B_LO_W);
        #pragma unroll
        for (int m = 0; m < 4; m++) {
            int i4 = tid + 256 * m;
            int k  = i4 >> 4;
            int n4 = i4 & 15;
            float4 v = wg4[i4];
            float vv[4] = {v.x, v.y, v.z, v.w};
            #pragma unroll
            for (int e = 0; e < 4; e++) {
                int n = n4 * 4 + e;
                __half hi = __float2half(vv[e]);
                __half lo = __float2half(vv[e] - __half2float(hi));
                bh16[n * (PLANE_STRIDE * 2) + k] = hi;
                bl16[n * (PLANE_STRIDE * 2) + k] = lo;
            }
        }
    }
    __syncthreads();   // S1

    // ---- GEMM1: h_prime = A_f16 @ (B_hi + B_lo), warp tile 32x32 ----
    const int wm = (wid >> 1) * 32;
    const int wn = (wid & 1) * 32;
    float c[2][4][4];
    #pragma unroll
    for (int mt = 0; mt < 2; mt++)
        #pragma unroll
        for (int nt = 0; nt < 4; nt++)
            #pragma unroll
            for (int e = 0; e < 4; e++) c[mt][nt][e] = 0.f;

    const uint32_t sbase = smem_u32(dsw);
    const uint32_t aF  = sbase + (uint32_t)(A_F_W + (wm + (lane & 15)) * PLANE_STRIDE
                                            + 4 * (lane >> 4)) * 4u;
    const uint32_t bHI = sbase + (uint32_t)(B_HI_W + (wn + (lane & 7) + 8 * (lane >> 4)) * PLANE_STRIDE
                                            + 4 * ((lane >> 3) & 1)) * 4u;
    const uint32_t bLO = bHI + (uint32_t)(B_LO_W - B_HI_W) * 4u;

    #pragma unroll
    for (int ks = 0; ks < 4; ks++) {
        const uint32_t kb = (uint32_t)ks * 32u;
        uint32_t af[2][4], bhf[4][2], blf[4][2];
        ldsm4(af[0], aF + kb);
        ldsm4(af[1], aF + kb + 16u * PLANE_STRIDE * 4u);
        ldsm4(&bhf[0][0], bHI + kb);
        ldsm4(&bhf[2][0], bHI + kb + 16u * PLANE_STRIDE * 4u);
        ldsm4(&blf[0][0], bLO + kb);
        ldsm4(&blf[2][0], bLO + kb + 16u * PLANE_STRIDE * 4u);
        #pragma unroll
        for (int mt = 0; mt < 2; mt++)
            #pragma unroll
            for (int nt = 0; nt < 4; nt++) {
                mma_fp16(c[mt][nt], af[mt], bhf[nt]);
                mma_fp16(c[mt][nt], af[mt], blf[nt]);
            }
    }
    __syncthreads();   // S2: staging dead, region becomes P/HT/RED

    // ---- HT = h_prime^T fp16 [o][j] from register fragments ----
    {
        __half* hptr = (__half*)(dsw + HT_W);
        #pragma unroll
        for (int mt = 0; mt < 2; mt++) {
            int ja = wm + mt * 16 + (lane >> 2);
            #pragma unroll
            for (int nt = 0; nt < 4; nt++) {
                int o0 = wn + nt * 8 + 2 * (lane & 3);
                hptr[o0 * 136 + ja]           = __float2half(c[mt][nt][0]);
                hptr[(o0 + 1) * 136 + ja]     = __float2half(c[mt][nt][1]);
                hptr[o0 * 136 + ja + 8]       = __float2half(c[mt][nt][2]);
                hptr[(o0 + 1) * 136 + ja + 8] = __float2half(c[mt][nt][3]);
            }
        }
    }
    // ---- tanh-dot partials from registers (quad-shuffle reduce) ----
    {
        float2 as2[4], ad2[4];
        #pragma unroll
        for (int nt = 0; nt < 4; nt++) {
            int o0 = wn + nt * 8 + 2 * (lane & 3);
            as2[nt] = *(const float2*)&a_src[head * DOUT + o0];
            ad2[nt] = *(const float2*)&a_dst[head * DOUT + o0];
        }
        #pragma unroll
        for (int mt = 0; mt < 2; mt++) {
            float psA = 0.f, pdA = 0.f, psB = 0.f, pdB = 0.f;
            #pragma unroll
            for (int nt = 0; nt < 4; nt++) {
                float t0 = tanh_fast(c[mt][nt][0]);
                float t1 = tanh_fast(c[mt][nt][1]);
                float t2 = tanh_fast(c[mt][nt][2]);
                float t3 = tanh_fast(c[mt][nt][3]);
                psA = fmaf(t0, as2[nt].x, fmaf(t1, as2[nt].y, psA));
                pdA = fmaf(t0, ad2[nt].x, fmaf(t1, ad2[nt].y, pdA));
                psB = fmaf(t2, as2[nt].x, fmaf(t3, as2[nt].y, psB));
                pdB = fmaf(t2, ad2[nt].x, fmaf(t3, ad2[nt].y, pdB));
            }
            #pragma unroll
            for (int o = 1; o <= 2; o <<= 1) {
                psA += __shfl_xor_sync(0xffffffffu, psA, o);
                pdA += __shfl_xor_sync(0xffffffffu, pdA, o);
                psB += __shfl_xor_sync(0xffffffffu, psB, o);
                pdB += __shfl_xor_sync(0xffffffffu, pdB, o);
            }
            if ((lane & 3) == 0) {
                int ra = wm + mt * 16 + (lane >> 2);
                int hf = wid & 1;
                dsf[RED_W + ra * 2 + hf]             = psA;
                dsf[RED_W + 256 + ra * 2 + hf]       = pdA;
                dsf[RED_W + (ra + 8) * 2 + hf]       = psB;
                dsf[RED_W + 256 + (ra + 8) * 2 + hf] = pdB;
            }
        }
    }
    __syncthreads();   // S3
    if (tid < NN) {
        dsf[SRC_W + tid] = dsf[RED_W + tid * 2] + dsf[RED_W + tid * 2 + 1];
        dsf[DST_W + tid] = dsf[RED_W + 256 + tid * 2] + dsf[RED_W + 256 + tid * 2 + 1];
    }
    __syncthreads();   // S4  (RED temps dead; DEN reuse safe)

    // ---- P/GEMM2 in two j-halves (P half = [128][36 words]) ----
    float c2[2][4][4];
    #pragma unroll
    for (int mt = 0; mt < 2; mt++)
        #pragma unroll
        for (int nt = 0; nt < 4; nt++)
            #pragma unroll
            for (int e = 0; e < 4; e++) c2[mt][nt][e] = 0.f;
    float cd[2][4] = {{0.f, 0.f, 0.f, 0.f}, {0.f, 0.f, 0.f, 0.f}};
    const uint32_t onesw = ((lane >> 2) == 0) ? 0x3C003C00u : 0u;  // fp16 1.0 pair, col n=0
    const uint32_t bones[2] = {onesw, onesw};

    const uint32_t pA = sbase + (uint32_t)(P_W + (wm + (lane & 15)) * PLANE_STRIDE
                                           + 4 * (lane >> 4)) * 4u;
    const uint32_t hB = sbase + (uint32_t)(HT_W + (wn + (lane & 7) + 8 * (lane >> 4)) * 68
                                           + 4 * ((lane >> 3) & 1)) * 4u;
    const int2* adjb2 = (const int2*)(adj + (size_t)b * NN * NN);

    #pragma unroll
    for (int r = 0; r < 2; r++) {
        if (r) __syncthreads();              // prior GEMM2 round done reading P
        // P-pass for j in [r*64, r*64+64): lane owns 2 j
        {
            const float2 dv = *(const float2*)&dsf[DST_W + r * 64 + 2 * lane];
            #pragma unroll 2
            for (int t = 0; t < 16; t++) {
                const int i = wid * 16 + t;
                int2 av = adjb2[i * 64 + r * 32 + lane];
                const float src_i = dsf[SRC_W + i];
                float e0 = src_i + dv.x; e0 = (e0 > 0.f) ? e0 : 0.2f * e0;
                float e1 = src_i + dv.y; e1 = (e1 > 0.f) ? e1 : 0.2f * e1;
                float p0 = av.x ? __expf(e0) : 0.f;
                float p1 = av.y ? __expf(e1) : 0.f;
                __half2 hp = __floats2half2_rn(p0, p1);
                dsw[P_W + i * PLANE_STRIDE + lane] = *(uint32_t*)&hp;
            }
        }
        __syncthreads();                     // P half ready
        // GEMM2 partial: ksteps r*4 .. r*4+3
        #pragma unroll
        for (int ksl = 0; ksl < 4; ksl++) {
            const uint32_t kb = (uint32_t)ksl * 32u;
            uint32_t af2[2][4], bf[4][2];
            ldsm4(af2[0], pA + kb);
            ldsm4(af2[1], pA + kb + 16u * PLANE_STRIDE * 4u);
            ldsm4(&bf[0][0], hB + (uint32_t)r * 128u + kb);
            ldsm4(&bf[2][0], hB + (uint32_t)r * 128u + kb + 16u * 68u * 4u);
            #pragma unroll
            for (int mt = 0; mt < 2; mt++)
                #pragma unroll
                for (int nt = 0; nt < 4; nt++)
                    mma_fp16(c2[mt][nt], af2[mt], bf[nt]);
            if ((wid & 1) == 0) {
                mma_fp16(cd[0], af2[0], bones);
                mma_fp16(cd[1], af2[1], bones);
            }
        }
    }

    // denom[row] from ones-MMA (col 0 lives at lane&3==0)
    if ((wid & 1) == 0 && (lane & 3) == 0) {
        int ra = wm + (lane >> 2);
        dsf[DEN_W + ra]      = cd[0][0];
        dsf[DEN_W + ra + 8]  = cd[0][2];
        dsf[DEN_W + ra + 16] = cd[1][0];
        dsf[DEN_W + ra + 24] = cd[1][2];
    }
    __syncthreads();   // S6

    // ---- epilogue: scale by 1/denom, + bias, write out ----
    {
        float* outp = out + (size_t)bh * NN * DOUT;
        #pragma unroll
        for (int mt = 0; mt < 2; mt++) {
            int ra = wm + mt * 16 + (lane >> 2);
            float d0 = dsf[DEN_W + ra];
            float d1 = dsf[DEN_W + ra + 8];
            float inv0 = (d0 > 0.f) ? (1.0f / d0) : 0.f;
            float inv1 = (d1 > 0.f) ? (1.0f / d1) : 0.f;
            #pragma unroll
            for (int nt = 0; nt < 4; nt++) {
                int o0 = wn + nt * 8 + 2 * (lane & 3);
                float2 bv = *(const float2*)&dsf[BIAS_W + o0];
                *(float2*)&outp[ra * DOUT + o0] =
                    make_float2(fmaf(c2[mt][nt][0], inv0, bv.x),
                                fmaf(c2[mt][nt][1], inv0, bv.y));
                *(float2*)&outp[(ra + 8) * DOUT + o0] =
                    make_float2(fmaf(c2[mt][nt][2], inv1, bv.x),
                                fmaf(c2[mt][nt][3], inv1, bv.y));
            }
        }
    }
}

extern "C" void kernel_launch(void* const* d_in, const int* in_sizes, int n_in,
                              void* d_out, int out_size) {
    const float* h     = (const float*)d_in[0];
    const int*   adj   = (const int*)d_in[1];
    const float* w     = (const float*)d_in[2];
    const float* a_src = (const float*)d_in[3];
    const float* a_dst = (const float*)d_in[4];
    const float* bias  = (const float*)d_in[5];
    float*       out   = (float*)d_out;

    static bool attr_set = false;
    if (!attr_set) {
        cudaFuncSetAttribute(gat_tc6, cudaFuncAttributeMaxDynamicSharedMemorySize, DSMEM_BYTES);
        attr_set = true;
    }
    gat_tc6<<<BS * HEADS, 256, DSMEM_BYTES>>>(h, adj, w, a_src, a_dst, bias, out);
}

// round 15
// speedup vs baseline: 1.7353x; 1.7353x over previous
#include <cuda_runtime.h>
#include <cuda_fp16.h>
#include <cstdint>
#include <math.h>

#define BS 512
#define NN 128
#define HEADS 8
#define DIN 64
#define DOUT 64

// ---- dynamic smem word layout ----
// Phase A staging (dead after GEMM1):
//   A_F  [128 rows][36 words] fp16 h              [0, 4608)
//   B_HI [64 n][36 words] fp16 hi(w)              [4608, 6912)
//   B_LO [64 n][36 words] fp16 lo(w)              [6912, 9216)
// Phase B (overlays staging):
//   P    [128 i][36 words] fp16 exp, one 64-j half at a time   [0, 4608)
//   HT   [64 o][68 words] fp16 h_prime^T (full K=128)          [4608, 8960)
//   RED  ps[256] pd[256] temps; DEN[128] reuse                 [8960, 9472)
#define PLANE_STRIDE 36
#define A_F_W  0
#define B_HI_W 4608
#define B_LO_W 6912
#define P_W    0
#define HT_W   4608
#define RED_W  8960
#define DEN_W  8960
#define SRC_W  9472
#define DST_W  9600
#define BIAS_W 9728
#define TOTAL_W 9792
#define DSMEM_BYTES (TOTAL_W * 4)

__device__ __forceinline__ float tanh_fast(float x) {
    float y;
    asm("tanh.approx.f32 %0, %1;" : "=f"(y) : "f"(x));
    return y;
}
__device__ __forceinline__ uint32_t smem_u32(const void* p) {
    return (uint32_t)__cvta_generic_to_shared(p);
}
__device__ __forceinline__ void mma_fp16(float c[4], const uint32_t a[4], const uint32_t b[2]) {
    asm volatile(
        "mma.sync.aligned.m16n8k16.row.col.f32.f16.f16.f32 "
        "{%0,%1,%2,%3}, {%4,%5,%6,%7}, {%8,%9}, {%0,%1,%2,%3};"
        : "+f"(c[0]), "+f"(c[1]), "+f"(c[2]), "+f"(c[3])
        : "r"(a[0]), "r"(a[1]), "r"(a[2]), "r"(a[3]), "r"(b[0]), "r"(b[1]));
}
__device__ __forceinline__ void ldsm4(uint32_t* r, uint32_t a) {
    asm volatile("ldmatrix.sync.aligned.m8n8.x4.shared.b16 {%0,%1,%2,%3}, [%4];"
                 : "=r"(r[0]), "=r"(r[1]), "=r"(r[2]), "=r"(r[3]) : "r"(a));
}

__global__ __launch_bounds__(256, 4)
void gat_tc7(const float* __restrict__ h,
             const int* __restrict__ adj,
             const float* __restrict__ w,
             const float* __restrict__ a_src,
             const float* __restrict__ a_dst,
             const float* __restrict__ bias,
             float* __restrict__ out)
{
    extern __shared__ uint32_t dsw[];
    float* dsf = (float*)dsw;

    const int bh   = blockIdx.x;
    const int b    = bh >> 3;
    const int head = bh & 7;
    const int tid  = threadIdx.x;
    const int lane = tid & 31;
    const int wid  = tid >> 5;

    if (tid < DOUT) dsf[BIAS_W + tid] = bias[tid];

    // ---- stage A = h[b] (128x64) -> single fp16 plane ----
    {
        const float4* hg4 = (const float4*)(h + (size_t)b * NN * DIN);
        #pragma unroll
        for (int m = 0; m < 8; m++) {
            int i4  = tid + 256 * m;
            int row = i4 >> 4;
            int c4  = i4 & 15;
            float4 v = hg4[i4];
            __half2 h01 = __floats2half2_rn(v.x, v.y);
            __half2 h23 = __floats2half2_rn(v.z, v.w);
            *(uint2*)(dsw + A_F_W + row * PLANE_STRIDE + c4 * 2) =
                make_uint2(*(uint32_t*)&h01, *(uint32_t*)&h23);
        }
    }
    // ---- stage B = w[head] ([k][n]) -> transposed fp16 hi/lo planes [n][k] ----
    {
        const float4* wg4 = (const float4*)(w + (size_t)head * DIN * DOUT);
        __half* bh16 = (__half*)(dsw + B_HI_W);
        __half* bl16 = (__half*)(dsw + B_LO_W);
        #pragma unroll
        for (int m = 0; m < 4; m++) {
            int i4 = tid + 256 * m;
            int k  = i4 >> 4;
            int n4 = i4 & 15;
            float4 v = wg4[i4];
            float vv[4] = {v.x, v.y, v.z, v.w};
            #pragma unroll
            for (int e = 0; e < 4; e++) {
                int n = n4 * 4 + e;
                __half hi = __float2half(vv[e]);
                __half lo = __float2half(vv[e] - __half2float(hi));
                bh16[n * (PLANE_STRIDE * 2) + k] = hi;
                bl16[n * (PLANE_STRIDE * 2) + k] = lo;
            }
        }
    }
    __syncthreads();   // S1

    // ---- GEMM1: h_prime = A_f16 @ (B_hi + B_lo), warp tile 32x32 ----
    const int wm = (wid >> 1) * 32;
    const int wn = (wid & 1) * 32;
    float c[2][4][4];
    #pragma unroll
    for (int mt = 0; mt < 2; mt++)
        #pragma unroll
        for (int nt = 0; nt < 4; nt++)
            #pragma unroll
            for (int e = 0; e < 4; e++) c[mt][nt][e] = 0.f;

    const uint32_t sbase = smem_u32(dsw);
    const uint32_t aF  = sbase + (uint32_t)(A_F_W + (wm + (lane & 15)) * PLANE_STRIDE
                                            + 4 * (lane >> 4)) * 4u;
    const uint32_t bHI = sbase + (uint32_t)(B_HI_W + (wn + (lane & 7) + 8 * (lane >> 4)) * PLANE_STRIDE
                                            + 4 * ((lane >> 3) & 1)) * 4u;
    const uint32_t bLO = bHI + (uint32_t)(B_LO_W - B_HI_W) * 4u;

    #pragma unroll
    for (int ks = 0; ks < 4; ks++) {
        const uint32_t kb = (uint32_t)ks * 32u;
        uint32_t af[2][4], bhf[4][2], blf[4][2];
        ldsm4(af[0], aF + kb);
        ldsm4(af[1], aF + kb + 16u * PLANE_STRIDE * 4u);
        ldsm4(&bhf[0][0], bHI + kb);
        ldsm4(&bhf[2][0], bHI + kb + 16u * PLANE_STRIDE * 4u);
        ldsm4(&blf[0][0], bLO + kb);
        ldsm4(&blf[2][0], bLO + kb + 16u * PLANE_STRIDE * 4u);
        #pragma unroll
        for (int mt = 0; mt < 2; mt++)
            #pragma unroll
            for (int nt = 0; nt < 4; nt++) {
                mma_fp16(c[mt][nt], af[mt], bhf[nt]);
                mma_fp16(c[mt][nt], af[mt], blf[nt]);
            }
    }
    __syncthreads();   // S2: staging dead, region becomes P/HT/RED

    // ---- HT = h_prime^T fp16 [o][j] from register fragments ----
    {
        __half* hptr = (__half*)(dsw + HT_W);
        #pragma unroll
        for (int mt = 0; mt < 2; mt++) {
            int ja = wm + mt * 16 + (lane >> 2);
            #pragma unroll
            for (int nt = 0; nt < 4; nt++) {
                int o0 = wn + nt * 8 + 2 * (lane & 3);
                hptr[o0 * 136 + ja]           = __float2half(c[mt][nt][0]);
                hptr[(o0 + 1) * 136 + ja]     = __float2half(c[mt][nt][1]);
                hptr[o0 * 136 + ja + 8]       = __float2half(c[mt][nt][2]);
                hptr[(o0 + 1) * 136 + ja + 8] = __float2half(c[mt][nt][3]);
            }
        }
    }
    // ---- tanh-dot partials from registers (quad-shuffle reduce) ----
    {
        float2 as2[4], ad2[4];
        #pragma unroll
        for (int nt = 0; nt < 4; nt++) {
            int o0 = wn + nt * 8 + 2 * (lane & 3);
            as2[nt] = *(const float2*)&a_src[head * DOUT + o0];
            ad2[nt] = *(const float2*)&a_dst[head * DOUT + o0];
        }
        #pragma unroll
        for (int mt = 0; mt < 2; mt++) {
            float psA = 0.f, pdA = 0.f, psB = 0.f, pdB = 0.f;
            #pragma unroll
            for (int nt = 0; nt < 4; nt++) {
                float t0 = tanh_fast(c[mt][nt][0]);
                float t1 = tanh_fast(c[mt][nt][1]);
                float t2 = tanh_fast(c[mt][nt][2]);
                float t3 = tanh_fast(c[mt][nt][3]);
                psA = fmaf(t0, as2[nt].x, fmaf(t1, as2[nt].y, psA));
                pdA = fmaf(t0, ad2[nt].x, fmaf(t1, ad2[nt].y, pdA));
                psB = fmaf(t2, as2[nt].x, fmaf(t3, as2[nt].y, psB));
                pdB = fmaf(t2, ad2[nt].x, fmaf(t3, ad2[nt].y, pdB));
            }
            #pragma unroll
            for (int o = 1; o <= 2; o <<= 1) {
                psA += __shfl_xor_sync(0xffffffffu, psA, o);
                pdA += __shfl_xor_sync(0xffffffffu, pdA, o);
                psB += __shfl_xor_sync(0xffffffffu, psB, o);
                pdB += __shfl_xor_sync(0xffffffffu, pdB, o);
            }
            if ((lane & 3) == 0) {
                int ra = wm + mt * 16 + (lane >> 2);
                int hf = wid & 1;
                dsf[RED_W + ra * 2 + hf]             = psA;
                dsf[RED_W + 256 + ra * 2 + hf]       = pdA;
                dsf[RED_W + (ra + 8) * 2 + hf]       = psB;
                dsf[RED_W + 256 + (ra + 8) * 2 + hf] = pdB;
            }
        }
    }
    __syncthreads();   // S3
    if (tid < NN) {
        dsf[SRC_W + tid] = dsf[RED_W + tid * 2] + dsf[RED_W + tid * 2 + 1];
        dsf[DST_W + tid] = dsf[RED_W + 256 + tid * 2] + dsf[RED_W + 256 + tid * 2 + 1];
    }
    __syncthreads();   // S4  (RED temps dead; DEN reuse safe)

    // ---- P/GEMM2 in two j-halves (P half = [128][36 words]) ----
    float c2[2][4][4];
    #pragma unroll
    for (int mt = 0; mt < 2; mt++)
        #pragma unroll
        for (int nt = 0; nt < 4; nt++)
            #pragma unroll
            for (int e = 0; e < 4; e++) c2[mt][nt][e] = 0.f;
    float cd[2][4] = {{0.f, 0.f, 0.f, 0.f}, {0.f, 0.f, 0.f, 0.f}};
    const uint32_t onesw = ((lane >> 2) == 0) ? 0x3C003C00u : 0u;  // fp16 1.0 pair, col n=0
    const uint32_t bones[2] = {onesw, onesw};

    const uint32_t pA = sbase + (uint32_t)(P_W + (wm + (lane & 15)) * PLANE_STRIDE
                                           + 4 * (lane >> 4)) * 4u;
    const uint32_t hB = sbase + (uint32_t)(HT_W + (wn + (lane & 7) + 8 * (lane >> 4)) * 68
                                           + 4 * ((lane >> 3) & 1)) * 4u;
    const int2* adjb2 = (const int2*)(adj + (size_t)b * NN * NN);

    #pragma unroll
    for (int r = 0; r < 2; r++) {
        if (r) __syncthreads();              // prior GEMM2 round done reading P
        // P-pass for j in [r*64, r*64+64): lane owns 2 j
        {
            const float2 dv = *(const float2*)&dsf[DST_W + r * 64 + 2 * lane];
            #pragma unroll 2
            for (int t = 0; t < 16; t++) {
                const int i = wid * 16 + t;
                int2 av = adjb2[i * 64 + r * 32 + lane];
                const float src_i = dsf[SRC_W + i];
                float e0 = src_i + dv.x; e0 = (e0 > 0.f) ? e0 : 0.2f * e0;
                float e1 = src_i + dv.y; e1 = (e1 > 0.f) ? e1 : 0.2f * e1;
                float p0 = av.x ? __expf(e0) : 0.f;
                float p1 = av.y ? __expf(e1) : 0.f;
                __half2 hp = __floats2half2_rn(p0, p1);
                dsw[P_W + i * PLANE_STRIDE + lane] = *(uint32_t*)&hp;
            }
        }
        __syncthreads();                     // P half ready
        // GEMM2 partial: ksteps over this half
        #pragma unroll
        for (int ksl = 0; ksl < 4; ksl++) {
            const uint32_t kb = (uint32_t)ksl * 32u;
            uint32_t af2[2][4], bf[4][2];
            ldsm4(af2[0], pA + kb);
            ldsm4(af2[1], pA + kb + 16u * PLANE_STRIDE * 4u);
            ldsm4(&bf[0][0], hB + (uint32_t)r * 128u + kb);
            ldsm4(&bf[2][0], hB + (uint32_t)r * 128u + kb + 16u * 68u * 4u);
            #pragma unroll
            for (int mt = 0; mt < 2; mt++)
                #pragma unroll
                for (int nt = 0; nt < 4; nt++)
                    mma_fp16(c2[mt][nt], af2[mt], bf[nt]);
            if ((wid & 1) == 0) {
                mma_fp16(cd[0], af2[0], bones);
                mma_fp16(cd[1], af2[1], bones);
            }
        }
    }

    // denom[row] from ones-MMA (col 0 lives at lane&3==0)
    if ((wid & 1) == 0 && (lane & 3) == 0) {
        int ra = wm + (lane >> 2);
        dsf[DEN_W + ra]      = cd[0][0];
        dsf[DEN_W + ra + 8]  = cd[0][2];
        dsf[DEN_W + ra + 16] = cd[1][0];
        dsf[DEN_W + ra + 24] = cd[1][2];
    }
    __syncthreads();   // S6

    // ---- epilogue: scale by 1/denom, + bias, write out ----
    {
        float* outp = out + (size_t)bh * NN * DOUT;
        #pragma unroll
        for (int mt = 0; mt < 2; mt++) {
            int ra = wm + mt * 16 + (lane >> 2);
            float d0 = dsf[DEN_W + ra];
            float d1 = dsf[DEN_W + ra + 8];
            float inv0 = (d0 > 0.f) ? (1.0f / d0) : 0.f;
            float inv1 = (d1 > 0.f) ? (1.0f / d1) : 0.f;
            #pragma unroll
            for (int nt = 0; nt < 4; nt++) {
                int o0 = wn + nt * 8 + 2 * (lane & 3);
                float2 bv = *(const float2*)&dsf[BIAS_W + o0];
                *(float2*)&outp[ra * DOUT + o0] =
                    make_float2(fmaf(c2[mt][nt][0], inv0, bv.x),
                                fmaf(c2[mt][nt][1], inv0, bv.y));
                *(float2*)&outp[(ra + 8) * DOUT + o0] =
                    make_float2(fmaf(c2[mt][nt][2], inv1, bv.x),
                                fmaf(c2[mt][nt][3], inv1, bv.y));
            }
        }
    }
}

extern "C" void kernel_launch(void* const* d_in, const int* in_sizes, int n_in,
                              void* d_out, int out_size) {
    const float* h     = (const float*)d_in[0];
    const int*   adj   = (const int*)d_in[1];
    const float* w     = (const float*)d_in[2];
    const float* a_src = (const float*)d_in[3];
    const float* a_dst = (const float*)d_in[4];
    const float* bias  = (const float*)d_in[5];
    float*       out   = (float*)d_out;

    static bool attr_set = false;
    if (!attr_set) {
        cudaFuncSetAttribute(gat_tc7, cudaFuncAttributeMaxDynamicSharedMemorySize, DSMEM_BYTES);
        attr_set = true;
    }
    gat_tc7<<<BS * HEADS, 256, DSMEM_BYTES>>>(h, adj, w, a_src, a_dst, bias, out);
}

// round 17
// speedup vs baseline: 1.8791x; 1.0828x over previous
#include <cuda_runtime.h>
#include <cuda_fp16.h>
#include <cstdint>
#include <math.h>

#define BS 512
#define NN 128
#define HEADS 8
#define DIN 64
#define DOUT 64

// ---- dynamic smem word layout ----
// Phase A staging (dead after GEMM1):
//   A_F  [128 rows][36 words] fp16 h              [0, 4608)
//   B_HI [64 n][36 words] fp16 hi(w)              [4608, 6912)
//   B_LO [64 n][36 words] fp16 lo(w)              [6912, 9216)
// Phase B (overlays staging):
//   P    [128 i][68 words] fp16 exp (full j width)   [0, 8704)
//   HT   [64 o][68 words] fp16 h_prime^T             [8704, 13056)
//   RED  ps[256]+pd[256] temps; DEN[128] reuse       [13056, 13568)
#define PLANE_STRIDE 36
#define A_F_W  0
#define B_HI_W 4608
#define B_LO_W 6912
#define P_W    0
#define HT_W   8704
#define RED_W  13056
#define DEN_W  13056
#define SRC_W  13568
#define DST_W  13696
#define BIAS_W 13824
#define TOTAL_W 13888
#define DSMEM_BYTES (TOTAL_W * 4)

__device__ __forceinline__ float tanh_fast(float x) {
    float y;
    asm("tanh.approx.f32 %0, %1;" : "=f"(y) : "f"(x));
    return y;
}
__device__ __forceinline__ uint32_t smem_u32(const void* p) {
    return (uint32_t)__cvta_generic_to_shared(p);
}
__device__ __forceinline__ void mma_fp16(float c[4], const uint32_t a[4], const uint32_t b[2]) {
    asm volatile(
        "mma.sync.aligned.m16n8k16.row.col.f32.f16.f16.f32 "
        "{%0,%1,%2,%3}, {%4,%5,%6,%7}, {%8,%9}, {%0,%1,%2,%3};"
        : "+f"(c[0]), "+f"(c[1]), "+f"(c[2]), "+f"(c[3])
        : "r"(a[0]), "r"(a[1]), "r"(a[2]), "r"(a[3]), "r"(b[0]), "r"(b[1]));
}
__device__ __forceinline__ void ldsm4(uint32_t* r, uint32_t a) {
    asm volatile("ldmatrix.sync.aligned.m8n8.x4.shared.b16 {%0,%1,%2,%3}, [%4];"
                 : "=r"(r[0]), "=r"(r[1]), "=r"(r[2]), "=r"(r[3]) : "r"(a));
}

__global__ __launch_bounds__(256, 4)
void gat_tc8(const float* __restrict__ h,
             const int* __restrict__ adj,
             const float* __restrict__ w,
             const float* __restrict__ a_src,
             const float* __restrict__ a_dst,
             const float* __restrict__ bias,
             float* __restrict__ out)
{
    extern __shared__ uint32_t dsw[];
    float* dsf = (float*)dsw;

    const int bh   = blockIdx.x;
    const int b    = bh >> 3;
    const int head = bh & 7;
    const int tid  = threadIdx.x;
    const int lane = tid & 31;
    const int wid  = tid >> 5;

    if (tid < DOUT) dsf[BIAS_W + tid] = bias[tid];

    // ---- stage A = h[b] (128x64) -> single fp16 plane ----
    {
        const float4* hg4 = (const float4*)(h + (size_t)b * NN * DIN);
        #pragma unroll
        for (int m = 0; m < 8; m++) {
            int i4  = tid + 256 * m;
            int row = i4 >> 4;
            int c4  = i4 & 15;
            float4 v = hg4[i4];
            __half2 h01 = __floats2half2_rn(v.x, v.y);
            __half2 h23 = __floats2half2_rn(v.z, v.w);
            *(uint2*)(dsw + A_F_W + row * PLANE_STRIDE + c4 * 2) =
                make_uint2(*(uint32_t*)&h01, *(uint32_t*)&h23);
        }
    }
    // ---- stage B = w[head] ([k][n]) -> transposed fp16 hi/lo planes [n][k] ----
    {
        const float4* wg4 = (const float4*)(w + (size_t)head * DIN * DOUT);
        __half* bh16 = (__half*)(dsw + B_HI_W);
        __half* bl16 = (__half*)(dsw + B_LO_W);
        #pragma unroll
        for (int m = 0; m < 4; m++) {
            int i4 = tid + 256 * m;
            int k  = i4 >> 4;
            int n4 = i4 & 15;
            float4 v = wg4[i4];
            float vv[4] = {v.x, v.y, v.z, v.w};
            #pragma unroll
            for (int e = 0; e < 4; e++) {
                int n = n4 * 4 + e;
                __half hi = __float2half(vv[e]);
                __half lo = __float2half(vv[e] - __half2float(hi));
                bh16[n * (PLANE_STRIDE * 2) + k] = hi;
                bl16[n * (PLANE_STRIDE * 2) + k] = lo;
            }
        }
    }
    __syncthreads();   // S1

    // ---- GEMM1: h_prime = A_f16 @ (B_hi + B_lo), warp tile 32x32 ----
    const int wm = (wid >> 1) * 32;
    const int wn = (wid & 1) * 32;
    float c[2][4][4];
    #pragma unroll
    for (int mt = 0; mt < 2; mt++)
        #pragma unroll
        for (int nt = 0; nt < 4; nt++)
            #pragma unroll
            for (int e = 0; e < 4; e++) c[mt][nt][e] = 0.f;

    const uint32_t sbase = smem_u32(dsw);
    const uint32_t aF  = sbase + (uint32_t)(A_F_W + (wm + (lane & 15)) * PLANE_STRIDE
                                            + 4 * (lane >> 4)) * 4u;
    const uint32_t bHI = sbase + (uint32_t)(B_HI_W + (wn + (lane & 7) + 8 * (lane >> 4)) * PLANE_STRIDE
                                            + 4 * ((lane >> 3) & 1)) * 4u;
    const uint32_t bLO = bHI + (uint32_t)(B_LO_W - B_HI_W) * 4u;

    #pragma unroll
    for (int ks = 0; ks < 4; ks++) {
        const uint32_t kb = (uint32_t)ks * 32u;
        uint32_t af[2][4], bhf[4][2], blf[4][2];
        ldsm4(af[0], aF + kb);
        ldsm4(af[1], aF + kb + 16u * PLANE_STRIDE * 4u);
        ldsm4(&bhf[0][0], bHI + kb);
        ldsm4(&bhf[2][0], bHI + kb + 16u * PLANE_STRIDE * 4u);
        ldsm4(&blf[0][0], bLO + kb);
        ldsm4(&blf[2][0], bLO + kb + 16u * PLANE_STRIDE * 4u);
        #pragma unroll
        for (int mt = 0; mt < 2; mt++)
            #pragma unroll
            for (int nt = 0; nt < 4; nt++) {
                mma_fp16(c[mt][nt], af[mt], bhf[nt]);
                mma_fp16(c[mt][nt], af[mt], blf[nt]);
            }
    }
    __syncthreads();   // S2: staging dead, region becomes P/HT/RED

    // ---- HT = h_prime^T fp16 [o][j] from register fragments ----
    {
        __half* hptr = (__half*)(dsw + HT_W);
        #pragma unroll
        for (int mt = 0; mt < 2; mt++) {
            int ja = wm + mt * 16 + (lane >> 2);
            #pragma unroll
            for (int nt = 0; nt < 4; nt++) {
                int o0 = wn + nt * 8 + 2 * (lane & 3);
                hptr[o0 * 136 + ja]           = __float2half(c[mt][nt][0]);
                hptr[(o0 + 1) * 136 + ja]     = __float2half(c[mt][nt][1]);
                hptr[o0 * 136 + ja + 8]       = __float2half(c[mt][nt][2]);
                hptr[(o0 + 1) * 136 + ja + 8] = __float2half(c[mt][nt][3]);
            }
        }
    }
    // ---- tanh-dot partials from registers (quad-shuffle reduce) ----
    {
        float2 as2[4], ad2[4];
        #pragma unroll
        for (int nt = 0; nt < 4; nt++) {
            int o0 = wn + nt * 8 + 2 * (lane & 3);
            as2[nt] = *(const float2*)&a_src[head * DOUT + o0];
            ad2[nt] = *(const float2*)&a_dst[head * DOUT + o0];
        }
        #pragma unroll
        for (int mt = 0; mt < 2; mt++) {
            float psA = 0.f, pdA = 0.f, psB = 0.f, pdB = 0.f;
            #pragma unroll
            for (int nt = 0; nt < 4; nt++) {
                float t0 = tanh_fast(c[mt][nt][0]);
                float t1 = tanh_fast(c[mt][nt][1]);
                float t2 = tanh_fast(c[mt][nt][2]);
                float t3 = tanh_fast(c[mt][nt][3]);
                psA = fmaf(t0, as2[nt].x, fmaf(t1, as2[nt].y, psA));
                pdA = fmaf(t0, ad2[nt].x, fmaf(t1, ad2[nt].y, pdA));
                psB = fmaf(t2, as2[nt].x, fmaf(t3, as2[nt].y, psB));
                pdB = fmaf(t2, ad2[nt].x, fmaf(t3, ad2[nt].y, pdB));
            }
            #pragma unroll
            for (int o = 1; o <= 2; o <<= 1) {
                psA += __shfl_xor_sync(0xffffffffu, psA, o);
                pdA += __shfl_xor_sync(0xffffffffu, pdA, o);
                psB += __shfl_xor_sync(0xffffffffu, psB, o);
                pdB += __shfl_xor_sync(0xffffffffu, pdB, o);
            }
            if ((lane & 3) == 0) {
                int ra = wm + mt * 16 + (lane >> 2);
                int hf = wid & 1;
                dsf[RED_W + ra * 2 + hf]             = psA;
                dsf[RED_W + 256 + ra * 2 + hf]       = pdA;
                dsf[RED_W + (ra + 8) * 2 + hf]       = psB;
                dsf[RED_W + 256 + (ra + 8) * 2 + hf] = pdB;
            }
        }
    }
    __syncthreads();   // S3
    if (tid < NN) {
        dsf[SRC_W + tid] = dsf[RED_W + tid * 2] + dsf[RED_W + tid * 2 + 1];
        dsf[DST_W + tid] = dsf[RED_W + 256 + tid * 2] + dsf[RED_W + 256 + tid * 2 + 1];
    }
    __syncthreads();   // S4

    // ---- P pass: UNNORMALIZED exp, full width, no reduction ----
    {
        const int4* adjb4 = (const int4*)(adj + (size_t)b * NN * NN);
        const float4 dv = *(const float4*)&dsf[DST_W + 4 * lane];
        #pragma unroll 2
        for (int t = 0; t < 16; t++) {
            const int i = wid * 16 + t;
            int4 av = adjb4[i * 32 + lane];
            const float src_i = dsf[SRC_W + i];

            float e0 = src_i + dv.x; e0 = (e0 > 0.f) ? e0 : 0.2f * e0;
            float e1 = src_i + dv.y; e1 = (e1 > 0.f) ? e1 : 0.2f * e1;
            float e2 = src_i + dv.z; e2 = (e2 > 0.f) ? e2 : 0.2f * e2;
            float e3 = src_i + dv.w; e3 = (e3 > 0.f) ? e3 : 0.2f * e3;
            float p0 = av.x ? __expf(e0) : 0.f;
            float p1 = av.y ? __expf(e1) : 0.f;
            float p2 = av.z ? __expf(e2) : 0.f;
            float p3 = av.w ? __expf(e3) : 0.f;

            __half2 h01 = __floats2half2_rn(p0, p1);
            __half2 h23 = __floats2half2_rn(p2, p3);
            *(uint2*)(dsw + P_W + i * 68 + 2 * lane) =
                make_uint2(*(uint32_t*)&h01, *(uint32_t*)&h23);
        }
    }
    __syncthreads();   // S5  (RED temps dead from here; DEN_W reuse safe)

    // ---- GEMM2: out_unnorm = P @ HT^T; denom via ones-column MMA ----
    float c2[2][4][4];
    #pragma unroll
    for (int mt = 0; mt < 2; mt++)
        #pragma unroll
        for (int nt = 0; nt < 4; nt++)
            #pragma unroll
            for (int e = 0; e < 4; e++) c2[mt][nt][e] = 0.f;
    float cd[2][4] = {{0.f, 0.f, 0.f, 0.f}, {0.f, 0.f, 0.f, 0.f}};
    const uint32_t onesw = ((lane >> 2) == 0) ? 0x3C003C00u : 0u;  // fp16 1.0 pair, col n=0
    const uint32_t bones[2] = {onesw, onesw};

    const uint32_t pA = sbase + (uint32_t)(P_W + (wm + (lane & 15)) * 68
                                           + 4 * (lane >> 4)) * 4u;
    const uint32_t hB = sbase + (uint32_t)(HT_W + (wn + (lane & 7) + 8 * (lane >> 4)) * 68
                                           + 4 * ((lane >> 3) & 1)) * 4u;

    #pragma unroll
    for (int ks = 0; ks < 8; ks++) {
        const uint32_t kb = (uint32_t)ks * 32u;
        uint32_t af2[2][4], bf[4][2];
        ldsm4(af2[0], pA + kb);
        ldsm4(af2[1], pA + kb + 16u * 68u * 4u);
        ldsm4(&bf[0][0], hB + kb);
        ldsm4(&bf[2][0], hB + kb + 16u * 68u * 4u);
        #pragma unroll
        for (int mt = 0; mt < 2; mt++)
            #pragma unroll
            for (int nt = 0; nt < 4; nt++)
                mma_fp16(c2[mt][nt], af2[mt], bf[nt]);
        if ((wid & 1) == 0) {
            mma_fp16(cd[0], af2[0], bones);
            mma_fp16(cd[1], af2[1], bones);
        }
    }

    // denom[row] from ones-MMA (col 0 lives at lane&3==0)
    if ((wid & 1) == 0 && (lane & 3) == 0) {
        int ra = wm + (lane >> 2);
        dsf[DEN_W + ra]      = cd[0][0];
        dsf[DEN_W + ra + 8]  = cd[0][2];
        dsf[DEN_W + ra + 16] = cd[1][0];
        dsf[DEN_W + ra + 24] = cd[1][2];
    }
    __syncthreads();   // S6

    // ---- epilogue: scale by 1/denom, + bias, write out ----
    {
        float* outp = out + (size_t)bh * NN * DOUT;
        #pragma unroll
        for (int mt = 0; mt < 2; mt++) {
            int ra = wm + mt * 16 + (lane >> 2);
            float d0 = dsf[DEN_W + ra];
            float d1 = dsf[DEN_W + ra + 8];
            float inv0 = (d0 > 0.f) ? (1.0f / d0) : 0.f;
            float inv1 = (d1 > 0.f) ? (1.0f / d1) : 0.f;
            #pragma unroll
            for (int nt = 0; nt < 4; nt++) {
                int o0 = wn + nt * 8 + 2 * (lane & 3);
                float2 bv = *(const float2*)&dsf[BIAS_W + o0];
                *(float2*)&outp[ra * DOUT + o0] =
                    make_float2(fmaf(c2[mt][nt][0], inv0, bv.x),
                                fmaf(c2[mt][nt][1], inv0, bv.y));
                *(float2*)&outp[(ra + 8) * DOUT + o0] =
                    make_float2(fmaf(c2[mt][nt][2], inv1, bv.x),
                                fmaf(c2[mt][nt][3], inv1, bv.y));
            }
        }
    }
}

extern "C" void kernel_launch(void* const* d_in, const int* in_sizes, int n_in,
                              void* d_out, int out_size) {
    const float* h     = (const float*)d_in[0];
    const int*   adj   = (const int*)d_in[1];
    const float* w     = (const float*)d_in[2];
    const float* a_src = (const float*)d_in[3];
    const float* a_dst = (const float*)d_in[4];
    const float* bias  = (const float*)d_in[5];
    float*       out   = (float*)d_out;

    static bool attr_set = false;
    if (!attr_set) {
        cudaFuncSetAttribute(gat_tc8, cudaFuncAttributeMaxDynamicSharedMemorySize, DSMEM_BYTES);
        attr_set = true;
    }
    gat_tc8<<<BS * HEADS, 256, DSMEM_BYTES>>>(h, adj, w, a_src, a_dst, bias, out);
}